// round 16
// baseline (speedup 1.0000x reference)
#include <cuda_runtime.h>
#include <cuda_fp16.h>
#include <cstdint>
#include <cstddef>

#define NN    100000
#define IND   128
#define HID   64
#define OUTD  128
#define ECAP  1700000
#define SCAN_B 256
#define NPART ((NN + SCAN_B - 1) / SCAN_B)   // 391

#define BM 128
#define KPAD 136    // stride in halves; conflict-free fragment LDS
#define MM_SMEM (2 * 128 * KPAD * (int)sizeof(__half))   // 69632 B

// Scratch (device globals — no allocation allowed). Node features in fp16.
__device__ __align__(16) __half g_yx [(size_t)NN * 128]; // 0-63: y1, 64-127: xr
__device__ __align__(16) __half g_cat[(size_t)NN * 128]; // 0-63: mh, 64-127: h
__device__ __align__(16) __half g_wt[2][128][128];       // fp16 W, [layer][n][k]
__device__ __align__(16) float g_rinv[NN];
__device__ __align__(16) int   g_deg[NN];
__device__ int   g_cur[NN];
__device__ int   g_off[NN + 1];
__device__ int   g_part[NPART];
__device__ int   g_poff[NPART];
__device__ int   g_eidx[ECAP];

// ---------------------------------------------------------------------------
__device__ __forceinline__ void mma_f16(float* d, const uint32_t* a,
                                        const uint32_t* b) {
    asm("mma.sync.aligned.m16n8k16.row.col.f32.f16.f16.f32 "
        "{%0,%1,%2,%3}, {%4,%5,%6,%7}, {%8,%9}, {%0,%1,%2,%3};"
        : "+f"(d[0]), "+f"(d[1]), "+f"(d[2]), "+f"(d[3])
        : "r"(a[0]), "r"(a[1]), "r"(a[2]), "r"(a[3]),
          "r"(b[0]), "r"(b[1]));
}

// ---------------------------------------------------------------------------
__global__ void k_init() {
    int i = blockIdx.x * blockDim.x + threadIdx.x;
    if (i < NN) g_deg[i] = 0;
}

__global__ void k_deg(const int* __restrict__ dst, int E) {
    int e = blockIdx.x * blockDim.x + threadIdx.x;
    if (e < E) {
        int d = dst[e];
        if (d >= 0 && d < NN) atomicAdd(&g_deg[d], 1);
    }
}

// ---------------------------------------------------------------------------
// One-time W convert/transpose to fp16 [n][k] (both layers).
// ---------------------------------------------------------------------------
__global__ __launch_bounds__(256) void k_prepw(
    const float* __restrict__ w1l, const float* __restrict__ w1r,
    const float* __restrict__ w2l, const float* __restrict__ w2r)
{
    int idx = blockIdx.x * blockDim.x + threadIdx.x;   // 0..32767
    if (idx >= 2 * 128 * 128) return;
    int which = idx >> 14;
    int r = (idx >> 7) & 127;   // n
    int c = idx & 127;          // k
    float v;
    if (which == 0)
        v = (r < 64) ? w1l[(size_t)c * 64 + r] : w1r[(size_t)c * 64 + (r - 64)];
    else
        v = (c < 64) ? w2l[(size_t)c * 128 + r] : w2r[(size_t)(c - 64) * 128 + r];
    g_wt[which][r][c] = __float2half_rn(v);
}

// ---------------------------------------------------------------------------
// Multi-block scan (3 phases)
// ---------------------------------------------------------------------------
__global__ __launch_bounds__(SCAN_B) void k_scan_part() {
    __shared__ int sred[SCAN_B];
    int t = threadIdx.x;
    int i = blockIdx.x * SCAN_B + t;
    sred[t] = (i < NN) ? g_deg[i] : 0;
    __syncthreads();
#pragma unroll
    for (int s = SCAN_B / 2; s > 0; s >>= 1) {
        if (t < s) sred[t] += sred[t + s];
        __syncthreads();
    }
    if (t == 0) g_part[blockIdx.x] = sred[0];
}

__global__ __launch_bounds__(512) void k_scan_top() {
    __shared__ int ss[512];
    int t = threadIdx.x;
    ss[t] = (t < NPART) ? g_part[t] : 0;
    __syncthreads();
#pragma unroll
    for (int d = 1; d < 512; d <<= 1) {
        int v = (t >= d) ? ss[t - d] : 0;
        __syncthreads();
        ss[t] += v;
        __syncthreads();
    }
    if (t < NPART) g_poff[t] = (t == 0) ? 0 : ss[t - 1];
}

__global__ __launch_bounds__(SCAN_B) void k_scan_off() {
    __shared__ int ss[SCAN_B];
    int t = threadIdx.x;
    int i = blockIdx.x * SCAN_B + t;
    int d = (i < NN) ? g_deg[i] : 0;
    ss[t] = d;
    __syncthreads();
#pragma unroll
    for (int s = 1; s < SCAN_B; s <<= 1) {
        int v = (t >= s) ? ss[t - s] : 0;
        __syncthreads();
        ss[t] += v;
        __syncthreads();
    }
    if (i < NN) {
        int off = g_poff[blockIdx.x] + ss[t] - d;
        g_off[i] = off;
        g_cur[i] = off;
        g_rinv[i] = 1.0f / fmaxf((float)d, 1.0f);
        if (i == NN - 1) g_off[NN] = off + d;
    }
}

__global__ void k_fill(const int* __restrict__ src,
                       const int* __restrict__ dst, int E) {
    int e = blockIdx.x * blockDim.x + threadIdx.x;
    if (e >= E) return;
    int d = dst[e];
    int s = src[e];
    if (d < 0 || d >= NN || s < 0 || s >= NN) return;
    int pos = atomicAdd(&g_cur[d], 1);
    if (pos >= 0 && pos < ECAP) g_eidx[pos] = s;
}

// ---------------------------------------------------------------------------
// fp16 tensor-core GEMM, single-stage full-K (BK=128):
//   C[n x 128] = A[n x 128] @ W[128 x 128]
// wmode 0: A = Ain (x fp32),  C = g_yx (fp16)
// wmode 1: A = g_cat (fp16),  C = Cout (fp32) + bias
// ---------------------------------------------------------------------------
__global__ __launch_bounds__(256, 2) void k_mm(
    const float* __restrict__ Ain,
    const float* __restrict__ bias,
    float* __restrict__ Cout,
    int n, int wmode)
{
    extern __shared__ __half smem[];
    __half* As = smem;                  // [128][KPAD]
    __half* Ws = smem + 128 * KPAD;     // [128][KPAD]

    int tid  = threadIdx.x;
    int wid  = tid >> 5;
    int lane = tid & 31;
    int grp  = lane >> 2;
    int qd   = lane & 3;
    int wm   = (wid >> 2) * 64;
    int wn   = (wid & 3) * 32;
    int m0   = blockIdx.x * BM;

    if (wmode == 0) {
#pragma unroll
        for (int l = 0; l < 8; l++) {
            int f = tid + l * 256;
            int r = f >> 4;
            int c8 = f & 15;
            int row = m0 + r;
            if (row >= n) row = n - 1;
            const float4* p = (const float4*)(Ain + (size_t)row * 128 + c8 * 8);
            float4 v0 = __ldg(p);
            float4 v1 = __ldg(p + 1);
            uint4 st;
            *(__half2*)&st.x = __floats2half2_rn(v0.x, v0.y);
            *(__half2*)&st.y = __floats2half2_rn(v0.z, v0.w);
            *(__half2*)&st.z = __floats2half2_rn(v1.x, v1.y);
            *(__half2*)&st.w = __floats2half2_rn(v1.z, v1.w);
            *(uint4*)&As[r * KPAD + c8 * 8] = st;
        }
    } else {
#pragma unroll
        for (int l = 0; l < 8; l++) {
            int f = tid + l * 256;
            int r = f >> 4;
            int c8 = f & 15;
            int row = m0 + r;
            if (row >= n) row = n - 1;
            uint4 u = *(const uint4*)(g_cat + (size_t)row * 128 + c8 * 8);
            *(uint4*)&As[r * KPAD + c8 * 8] = u;
        }
    }
    {
        const __half* wsrc = &g_wt[wmode][0][0];
#pragma unroll
        for (int l = 0; l < 8; l++) {
            int f = tid + l * 256;
            int nidx = f >> 4;
            int kq = f & 15;
            uint4 u = *(const uint4*)(wsrc + (size_t)nidx * 128 + kq * 8);
            *(uint4*)&Ws[nidx * KPAD + kq * 8] = u;
        }
    }
    __syncthreads();

    float acc[4][4][4];
#pragma unroll
    for (int i = 0; i < 4; i++)
#pragma unroll
        for (int j = 0; j < 4; j++)
#pragma unroll
            for (int r = 0; r < 4; r++) acc[i][j][r] = 0.f;

#pragma unroll
    for (int kk = 0; kk < 128; kk += 16) {
        uint32_t af[4][4];
#pragma unroll
        for (int mi = 0; mi < 4; mi++) {
            int mt = wm + mi * 16;
            af[mi][0] = *(const uint32_t*)&As[(mt + grp) * KPAD + kk + 2 * qd];
            af[mi][1] = *(const uint32_t*)&As[(mt + grp + 8) * KPAD + kk + 2 * qd];
            af[mi][2] = *(const uint32_t*)&As[(mt + grp) * KPAD + kk + 2 * qd + 8];
            af[mi][3] = *(const uint32_t*)&As[(mt + grp + 8) * KPAD + kk + 2 * qd + 8];
        }
        uint32_t bf[4][2];
#pragma unroll
        for (int ni = 0; ni < 4; ni++) {
            int nn = wn + ni * 8 + grp;
            bf[ni][0] = *(const uint32_t*)&Ws[nn * KPAD + kk + 2 * qd];
            bf[ni][1] = *(const uint32_t*)&Ws[nn * KPAD + kk + 2 * qd + 8];
        }
#pragma unroll
        for (int mi = 0; mi < 4; mi++)
#pragma unroll
            for (int ni = 0; ni < 4; ni++)
                mma_f16(acc[mi][ni], af[mi], bf[ni]);
    }

    if (wmode == 0) {
#pragma unroll
        for (int mi = 0; mi < 4; mi++) {
            int r0 = m0 + wm + mi * 16 + grp;
            int r1 = r0 + 8;
#pragma unroll
            for (int ni = 0; ni < 4; ni++) {
                int c = wn + ni * 8 + qd * 2;
                if (r0 < n)
                    *(__half2*)(g_yx + (size_t)r0 * 128 + c) =
                        __floats2half2_rn(acc[mi][ni][0], acc[mi][ni][1]);
                if (r1 < n)
                    *(__half2*)(g_yx + (size_t)r1 * 128 + c) =
                        __floats2half2_rn(acc[mi][ni][2], acc[mi][ni][3]);
            }
        }
    } else {
        float bb[4][2];
#pragma unroll
        for (int ni = 0; ni < 4; ni++) {
            int c = wn + ni * 8 + qd * 2;
            bb[ni][0] = __ldg(bias + c);
            bb[ni][1] = __ldg(bias + c + 1);
        }
#pragma unroll
        for (int mi = 0; mi < 4; mi++) {
            int r0 = m0 + wm + mi * 16 + grp;
            int r1 = r0 + 8;
#pragma unroll
            for (int ni = 0; ni < 4; ni++) {
                int c = wn + ni * 8 + qd * 2;
                if (r0 < n)
                    *(float2*)(Cout + (size_t)r0 * 128 + c) =
                        make_float2(acc[mi][ni][0] + bb[ni][0],
                                    acc[mi][ni][1] + bb[ni][1]);
                if (r1 < n)
                    *(float2*)(Cout + (size_t)r1 * 128 + c) =
                        make_float2(acc[mi][ni][2] + bb[ni][0],
                                    acc[mi][ni][3] + bb[ni][1]);
            }
        }
    }
}

// ---------------------------------------------------------------------------
// Gather-side aggregation, one warp per node, 4 edge streams (quarter-warps),
// uint4 (16B) loads: 8 lanes cover a 64-col fp16 row; 2x unroll -> 8 gathers
// in flight per warp. fp32 accumulation.
// layer 0: h  = relu(mean(y1[nbrs]) + b1 + xr)  -> g_cat[64:]
// layer 1: mh = mean(h[nbrs])                   -> g_cat[0:64]
// ---------------------------------------------------------------------------
__global__ __launch_bounds__(256) void k_agg(const float* __restrict__ b1,
                                             int layer)
{
    int node = blockIdx.x * 8 + (threadIdx.x >> 5);
    if (node >= NN) return;
    int lane = threadIdx.x & 31;
    int q    = lane & 7;      // uint4 slot (cols 8q..8q+7)
    int st   = lane >> 3;     // stream 0..3

    const __half* val = (layer == 0) ? g_yx : (g_cat + 64);
    int beg = g_off[node];
    int end = g_off[node + 1];

    float a[8] = {0.f, 0.f, 0.f, 0.f, 0.f, 0.f, 0.f, 0.f};
    float b[8] = {0.f, 0.f, 0.f, 0.f, 0.f, 0.f, 0.f, 0.f};
    int e = beg + st;
    for (; e + 4 < end; e += 8) {
        int s0 = __ldg(&g_eidx[e]);
        int s1 = __ldg(&g_eidx[e + 4]);
        uint4 u0 = *(const uint4*)(val + (size_t)s0 * 128 + q * 8);
        uint4 u1 = *(const uint4*)(val + (size_t)s1 * 128 + q * 8);
        float2 f0 = __half22float2(*(__half2*)&u0.x);
        float2 f1 = __half22float2(*(__half2*)&u0.y);
        float2 f2 = __half22float2(*(__half2*)&u0.z);
        float2 f3 = __half22float2(*(__half2*)&u0.w);
        a[0] += f0.x; a[1] += f0.y; a[2] += f1.x; a[3] += f1.y;
        a[4] += f2.x; a[5] += f2.y; a[6] += f3.x; a[7] += f3.y;
        float2 g0 = __half22float2(*(__half2*)&u1.x);
        float2 g1 = __half22float2(*(__half2*)&u1.y);
        float2 g2 = __half22float2(*(__half2*)&u1.z);
        float2 g3 = __half22float2(*(__half2*)&u1.w);
        b[0] += g0.x; b[1] += g0.y; b[2] += g1.x; b[3] += g1.y;
        b[4] += g2.x; b[5] += g2.y; b[6] += g3.x; b[7] += g3.y;
    }
    if (e < end) {
        int s = __ldg(&g_eidx[e]);
        uint4 u = *(const uint4*)(val + (size_t)s * 128 + q * 8);
        float2 f0 = __half22float2(*(__half2*)&u.x);
        float2 f1 = __half22float2(*(__half2*)&u.y);
        float2 f2 = __half22float2(*(__half2*)&u.z);
        float2 f3 = __half22float2(*(__half2*)&u.w);
        a[0] += f0.x; a[1] += f0.y; a[2] += f1.x; a[3] += f1.y;
        a[4] += f2.x; a[5] += f2.y; a[6] += f3.x; a[7] += f3.y;
    }
#pragma unroll
    for (int i = 0; i < 8; i++) {
        a[i] += b[i];
        a[i] += __shfl_xor_sync(0xffffffffu, a[i], 8);
        a[i] += __shfl_xor_sync(0xffffffffu, a[i], 16);
    }

    if (st == 0) {
        float r = g_rinv[node];
        if (layer == 0) {
            uint4 ux = *(const uint4*)(g_yx + (size_t)node * 128 + 64 + q * 8);
            float2 x0 = __half22float2(*(__half2*)&ux.x);
            float2 x1 = __half22float2(*(__half2*)&ux.y);
            float2 x2 = __half22float2(*(__half2*)&ux.z);
            float2 x3 = __half22float2(*(__half2*)&ux.w);
            float4 b0 = __ldg((const float4*)b1 + 2 * q);
            float4 b1v = __ldg((const float4*)b1 + 2 * q + 1);
            float h0 = fmaxf(fmaf(a[0], r, b0.x + x0.x), 0.f);
            float h1 = fmaxf(fmaf(a[1], r, b0.y + x0.y), 0.f);
            float h2 = fmaxf(fmaf(a[2], r, b0.z + x1.x), 0.f);
            float h3 = fmaxf(fmaf(a[3], r, b0.w + x1.y), 0.f);
            float h4 = fmaxf(fmaf(a[4], r, b1v.x + x2.x), 0.f);
            float h5 = fmaxf(fmaf(a[5], r, b1v.y + x2.y), 0.f);
            float h6 = fmaxf(fmaf(a[6], r, b1v.z + x3.x), 0.f);
            float h7 = fmaxf(fmaf(a[7], r, b1v.w + x3.y), 0.f);
            uint4 stv;
            *(__half2*)&stv.x = __floats2half2_rn(h0, h1);
            *(__half2*)&stv.y = __floats2half2_rn(h2, h3);
            *(__half2*)&stv.z = __floats2half2_rn(h4, h5);
            *(__half2*)&stv.w = __floats2half2_rn(h6, h7);
            *(uint4*)(g_cat + (size_t)node * 128 + 64 + q * 8) = stv;
        } else {
            uint4 stv;
            *(__half2*)&stv.x = __floats2half2_rn(a[0] * r, a[1] * r);
            *(__half2*)&stv.y = __floats2half2_rn(a[2] * r, a[3] * r);
            *(__half2*)&stv.z = __floats2half2_rn(a[4] * r, a[5] * r);
            *(__half2*)&stv.w = __floats2half2_rn(a[6] * r, a[7] * r);
            *(uint4*)(g_cat + (size_t)node * 128 + q * 8) = stv;
        }
    }
}

// ---------------------------------------------------------------------------
extern "C" void kernel_launch(void* const* d_in, const int* in_sizes, int n_in,
                              void* d_out, int out_size) {
    const float* x   = (const float*)d_in[0];
    const int*   ei  = (const int*)d_in[1];     // int32 edge_index [2, E]
    const float* w1l = (const float*)d_in[2];
    const float* b1  = (const float*)d_in[3];
    const float* w1r = (const float*)d_in[4];
    const float* w2l = (const float*)d_in[5];
    const float* b2  = (const float*)d_in[6];
    const float* w2r = (const float*)d_in[7];
    float* out = (float*)d_out;

    int E = in_sizes[1] / 2;
    const int* src = ei;
    const int* dst = ei + E;

    int mgrid = (NN + BM - 1) / BM;   // 782

    // One-time setup (host objects only; no device allocation).
    static cudaStream_t s2 = nullptr;
    static cudaEvent_t evFork = nullptr, evJoin = nullptr;
    if (s2 == nullptr) {
        cudaStreamCreateWithFlags(&s2, cudaStreamNonBlocking);
        cudaEventCreateWithFlags(&evFork, cudaEventDisableTiming);
        cudaEventCreateWithFlags(&evJoin, cudaEventDisableTiming);
        cudaFuncSetAttribute(k_mm, cudaFuncAttributeMaxDynamicSharedMemorySize,
                             MM_SMEM);
    }

    // Fork: weight prep + layer-1 GEMM on side stream, CSR build on main.
    cudaEventRecord(evFork, 0);
    cudaStreamWaitEvent(s2, evFork, 0);
    k_prepw<<<128, 256, 0, s2>>>(w1l, w1r, w2l, w2r);
    k_mm<<<mgrid, 256, MM_SMEM, s2>>>(x, nullptr, nullptr, NN, 0);
    cudaEventRecord(evJoin, s2);

    k_init<<<(NN + 511) / 512, 512>>>();
    k_deg <<<(E + 255) / 256, 256>>>(dst, E);
    k_scan_part<<<NPART, SCAN_B>>>();
    k_scan_top <<<1, 512>>>();
    k_scan_off <<<NPART, SCAN_B>>>();
    k_fill<<<(E + 255) / 256, 256>>>(src, dst, E);

    // Join: aggregation needs both CSR (main) and y1/xr (side).
    cudaStreamWaitEvent(0, evJoin, 0);

    k_agg<<<(NN + 7) / 8, 256>>>(b1, 0);
    k_agg<<<(NN + 7) / 8, 256>>>(b1, 1);

    // Layer-2 GEMM (+bias) straight to output
    k_mm<<<mgrid, 256, MM_SMEM>>>(nullptr, b2, out, NN, 1);
}